// round 1
// baseline (speedup 1.0000x reference)
#include <cuda_runtime.h>
#include <math.h>

// Problem constants
#define B_   4
#define N_   256      // d_model
#define Kd   128      // K dim of x
#define S_   256      // sequence length
#define BKt  512      // B_*Kd batches
#define SCALE 0.0625f // 1/sqrt(256)

// Scratch (device globals; allocation APIs are forbidden)
__device__ float g_peT[N_ * S_];                      // [n][s]
__device__ float g_hT [BKt * N_ * S_];                // [bk][n][s]   LN1+PE output (transposed)
__device__ float g_Qt [BKt * N_ * S_];                // [bk][j][s]
__device__ float g_Kt [BKt * N_ * S_];                // [bk][j][s]
__device__ float g_V  [BKt * N_ * S_];                // [bk][s][j]

// ---------------------------------------------------------------------------
// Kernel 0: positional encoding table, transposed layout peT[n][s]
// pe[s, 2i] = sin(s * exp(-2i*ln(1e4)/256)); pe[s, 2i+1] = cos(...)
// ---------------------------------------------------------------------------
__global__ void pe_kernel() {
    int n = blockIdx.x;
    int s = threadIdx.x;
    float i2   = (float)(n & ~1);
    float freq = __expf(-i2 * (9.210340371976184f / 256.0f)); // ln(10000)/256
    float a    = (float)s * freq;
    g_peT[n * S_ + s] = (n & 1) ? cosf(a) : sinf(a);
}

// ---------------------------------------------------------------------------
// Kernel 1: LN1 over n per (bk, s) row + PE, write transposed hT[bk][n][s].
// One CTA per batch bk; thread t = s. All global accesses coalesced.
// x index: ((b*N_ + n)*Kd + k)*S_ + s
// ---------------------------------------------------------------------------
__global__ void __launch_bounds__(256) ln1_kernel(const float* __restrict__ x,
                                                  const float* __restrict__ w1,
                                                  const float* __restrict__ b1) {
    int bk = blockIdx.x;
    int b  = bk >> 7;
    int k  = bk & 127;
    int s  = threadIdx.x;
    const float* xp = x + b * (N_ * Kd * S_) + k * S_ + s; // stride per n: Kd*S_ = 32768

    float sum = 0.f, sq = 0.f;
#pragma unroll 4
    for (int n = 0; n < N_; n++) {
        float v = xp[n * (Kd * S_)];
        sum += v; sq += v * v;
    }
    float mu  = sum * (1.f / N_);
    float var = sq * (1.f / N_) - mu * mu;
    float rs  = rsqrtf(var + 1e-5f);

    float* hp = g_hT + bk * (N_ * S_) + s;
#pragma unroll 4
    for (int n = 0; n < N_; n++) {
        float v = xp[n * (Kd * S_)];
        hp[n * S_] = (v - mu) * rs * w1[n] + b1[n] + g_peT[n * S_ + s];
    }
}

// ---------------------------------------------------------------------------
// Kernel 2: per-batch GEMMs.
//   which=0/1 (Q/K):  out[bk][j][s] = sum_n W[j][n] * hT[bk][n][s] + bias[j]
//   which=2   (V)  :  out[bk][s][j] = sum_n W[j][n] * hT[bk][n][s] + bias[j]
// Block tile 128x128, K-chunk 8, 8x8 micro-tile per thread (256 threads).
// ---------------------------------------------------------------------------
__global__ void __launch_bounds__(256) qkv_gemm(const float* __restrict__ qw,
                                                const float* __restrict__ kw,
                                                const float* __restrict__ vw,
                                                const float* __restrict__ qb,
                                                const float* __restrict__ kb,
                                                const float* __restrict__ vb) {
    __shared__ __align__(16) float Ws[8][136];
    __shared__ __align__(16) float Hs[8][136];

    int bk    = blockIdx.z;
    int which = blockIdx.y;
    int r0    = (blockIdx.x >> 1) * 128;  // output row tile
    int c0    = (blockIdx.x & 1) * 128;   // output col tile

    const float* W    = (which == 0) ? qw : (which == 1) ? kw : vw;
    const float* bias = (which == 0) ? qb : (which == 1) ? kb : vb;
    float* out        = (which == 0) ? g_Qt : (which == 1) ? g_Kt : g_V;
    bool vmode = (which == 2);

    int j0 = vmode ? c0 : r0;   // W-row tile
    int s0 = vmode ? r0 : c0;   // h-col tile

    int tid = threadIdx.x;
    int ty  = tid >> 4;      // 0..15 (row dir)
    int tx  = tid & 15;      // 0..15 (col dir)

    const float* hbase = g_hT + bk * (N_ * S_);

    int hR = tid >> 5;            // 0..7
    int hC = (tid & 31) * 4;      // 0..124
    int wJ = tid >> 1;            // 0..127
    int wH = (tid & 1) * 4;       // 0 or 4

    float acc[8][8] = {};

    for (int n0 = 0; n0 < N_; n0 += 8) {
        __syncthreads();
        // Hs[nn][ss] <- hT[n0+nn][s0+ss]  (coalesced)
        float4 hv = *(const float4*)(hbase + (n0 + hR) * S_ + s0 + hC);
        *(float4*)&Hs[hR][hC] = hv;
        // Ws[nn][jj] <- W[j0+jj][n0+nn]   (transpose on store)
        float4 wv = *(const float4*)(W + (j0 + wJ) * N_ + n0 + wH);
        Ws[wH + 0][wJ] = wv.x;
        Ws[wH + 1][wJ] = wv.y;
        Ws[wH + 2][wJ] = wv.z;
        Ws[wH + 3][wJ] = wv.w;
        __syncthreads();

#pragma unroll
        for (int nn = 0; nn < 8; nn++) {
            float rv[8], cv[8];
            if (!vmode) {
                *(float4*)(rv)     = *(float4*)&Ws[nn][ty * 8];
                *(float4*)(rv + 4) = *(float4*)&Ws[nn][ty * 8 + 4];
                *(float4*)(cv)     = *(float4*)&Hs[nn][tx * 8];
                *(float4*)(cv + 4) = *(float4*)&Hs[nn][tx * 8 + 4];
            } else {
                *(float4*)(rv)     = *(float4*)&Hs[nn][ty * 8];
                *(float4*)(rv + 4) = *(float4*)&Hs[nn][ty * 8 + 4];
                *(float4*)(cv)     = *(float4*)&Ws[nn][tx * 8];
                *(float4*)(cv + 4) = *(float4*)&Ws[nn][tx * 8 + 4];
            }
#pragma unroll
            for (int i = 0; i < 8; i++)
#pragma unroll
                for (int c = 0; c < 8; c++)
                    acc[i][c] += rv[i] * cv[c];
        }
    }

    float* obase = out + bk * (N_ * S_);
#pragma unroll
    for (int i = 0; i < 8; i++) {
        int r = r0 + ty * 8 + i;
        float vals[8];
#pragma unroll
        for (int c = 0; c < 8; c++) {
            int cc = c0 + tx * 8 + c;
            float bb = vmode ? bias[cc] : bias[r];
            vals[c] = acc[i][c] + bb;
        }
        *(float4*)(obase + r * S_ + c0 + tx * 8)     = *(float4*)(vals);
        *(float4*)(obase + r * S_ + c0 + tx * 8 + 4) = *(float4*)(vals + 4);
    }
}

// ---------------------------------------------------------------------------
// Kernel 3: fused attention + residual + LN2 + final residual (+x), per
// (batch bk, 64-row q-block). 256 threads = 8 warps; warp w owns q rows
// w*8..w*8+7 (full softmax row lives inside one warp -> register softmax).
// ---------------------------------------------------------------------------
#define SM_QS   0
#define SM_PS   16384                 // 64 x 264
#define SM_OS   (16384 + 16896)      // 64 x 264
#define SM_TS   (16384 + 2 * 16896)  // 8 x 264 streaming tile
#define SM_MU   (SM_TS + 2112)
#define SM_RS   (SM_MU + 64)
#define SM_FLOATS (SM_RS + 64)
#define SMEM_BYTES (SM_FLOATS * 4)

__global__ void __launch_bounds__(256) attn_kernel(const float* __restrict__ x,
                                                   float* __restrict__ out,
                                                   const float* __restrict__ w2,
                                                   const float* __restrict__ b2) {
    extern __shared__ __align__(16) float sm[];
    float* Qs  = sm + SM_QS;   // [256 j][64 q]
    float* Ps  = sm + SM_PS;   // [64 q][264] probs (later reused as Rs, stride 257)
    float* Os  = sm + SM_OS;   // [64 q][264] att@V
    float* Ts  = sm + SM_TS;   // [8][264] streamed K/V tile
    float* muA = sm + SM_MU;
    float* rsA = sm + SM_RS;

    int bk   = blockIdx.y;
    int q0   = blockIdx.x * 64;
    int tid  = threadIdx.x;
    int wq   = tid >> 5;   // warp id = q group
    int lane = tid & 31;

    const float* Qb = g_Qt + bk * (N_ * S_);
    const float* Kb = g_Kt + bk * (N_ * S_);
    const float* Vb = g_V  + bk * (N_ * S_);
    const float* hb = g_hT + bk * (N_ * S_);

    // Phase A: load Q block Qs[j][qi]
    for (int idx4 = tid; idx4 < 4096; idx4 += 256) {
        int j  = idx4 >> 4;
        int q4 = (idx4 & 15) * 4;
        *(float4*)&Qs[j * 64 + q4] = *(const float4*)(Qb + j * S_ + q0 + q4);
    }

    // Phase B: logits L[q][k] = sum_j Qt[j][q] * Kt[j][k]
    float acc[8][8] = {};
    for (int j0 = 0; j0 < N_; j0 += 8) {
        __syncthreads();
        for (int idx4 = tid; idx4 < 512; idx4 += 256) {
            int r  = idx4 >> 6;
            int c4 = (idx4 & 63) * 4;
            *(float4*)&Ts[r * 264 + c4] = *(const float4*)(Kb + (j0 + r) * S_ + c4);
        }
        __syncthreads();
#pragma unroll
        for (int jj = 0; jj < 8; jj++) {
            float qv[8], kv[8];
            *(float4*)(qv)     = *(float4*)&Qs[(j0 + jj) * 64 + wq * 8];
            *(float4*)(qv + 4) = *(float4*)&Qs[(j0 + jj) * 64 + wq * 8 + 4];
            *(float4*)(kv)     = *(float4*)&Ts[jj * 264 + lane * 8];
            *(float4*)(kv + 4) = *(float4*)&Ts[jj * 264 + lane * 8 + 4];
#pragma unroll
            for (int i = 0; i < 8; i++)
#pragma unroll
                for (int c = 0; c < 8; c++)
                    acc[i][c] += qv[i] * kv[c];
        }
    }

    // Register softmax per q row (row fully inside one warp), then *SCALE
#pragma unroll
    for (int i = 0; i < 8; i++) {
        float m = -1e30f;
#pragma unroll
        for (int c = 0; c < 8; c++) m = fmaxf(m, acc[i][c]);
#pragma unroll
        for (int o = 16; o > 0; o >>= 1) m = fmaxf(m, __shfl_xor_sync(0xffffffffu, m, o));
        float ssum = 0.f;
#pragma unroll
        for (int c = 0; c < 8; c++) { acc[i][c] = __expf(acc[i][c] - m); ssum += acc[i][c]; }
#pragma unroll
        for (int o = 16; o > 0; o >>= 1) ssum += __shfl_xor_sync(0xffffffffu, ssum, o);
        float f = SCALE / ssum;
#pragma unroll
        for (int c = 0; c < 8; c++) acc[i][c] *= f;
        *(float4*)&Ps[(wq * 8 + i) * 264 + lane * 8]     = *(float4*)&acc[i][0];
        *(float4*)&Ps[(wq * 8 + i) * 264 + lane * 8 + 4] = *(float4*)&acc[i][4];
    }

    // Phase C: O[q][d] = sum_k P[q][k] * V[k][d]
    float acc2[8][8] = {};
    for (int k0 = 0; k0 < S_; k0 += 8) {
        __syncthreads();
        for (int idx4 = tid; idx4 < 512; idx4 += 256) {
            int r  = idx4 >> 6;
            int c4 = (idx4 & 63) * 4;
            *(float4*)&Ts[r * 264 + c4] = *(const float4*)(Vb + (k0 + r) * S_ + c4);
        }
        __syncthreads();
#pragma unroll
        for (int kk = 0; kk < 8; kk++) {
            float pv[8], vv[8];
#pragma unroll
            for (int i = 0; i < 8; i++) pv[i] = Ps[(wq * 8 + i) * 264 + k0 + kk];
            *(float4*)(vv)     = *(float4*)&Ts[kk * 264 + lane * 8];
            *(float4*)(vv + 4) = *(float4*)&Ts[kk * 264 + lane * 8 + 4];
#pragma unroll
            for (int i = 0; i < 8; i++)
#pragma unroll
                for (int c = 0; c < 8; c++)
                    acc2[i][c] += pv[i] * vv[c];
        }
    }

    // Stage O to smem
#pragma unroll
    for (int i = 0; i < 8; i++) {
        *(float4*)&Os[(wq * 8 + i) * 264 + lane * 8]     = *(float4*)&acc2[i][0];
        *(float4*)&Os[(wq * 8 + i) * 264 + lane * 8 + 4] = *(float4*)&acc2[i][4];
    }
    __syncthreads();

    // Load residual tile Rs[qi][d] (reuse Ps region, stride 257: conflict-free)
    float* Rs = Ps;
    for (int idx = tid; idx < 16384; idx += 256) {
        int d  = idx >> 6;
        int qi = idx & 63;
        Rs[qi * 257 + d] = hb[d * S_ + q0 + qi];
    }
    __syncthreads();

    // LN2 stats per q row (warp wq handles rows wq*8..wq*8+7)
    for (int ri = 0; ri < 8; ri++) {
        int r = wq * 8 + ri;
        float s1 = 0.f, s2 = 0.f;
#pragma unroll
        for (int c = 0; c < 8; c++) {
            int d = lane * 8 + c;
            float v = Rs[r * 257 + d] + Os[r * 264 + d];
            s1 += v; s2 += v * v;
        }
#pragma unroll
        for (int o = 16; o > 0; o >>= 1) {
            s1 += __shfl_xor_sync(0xffffffffu, s1, o);
            s2 += __shfl_xor_sync(0xffffffffu, s2, o);
        }
        float mu  = s1 * (1.f / N_);
        float var = s2 * (1.f / N_) - mu * mu;
        muA[r] = mu;
        rsA[r] = rsqrtf(var + 1e-5f);
    }
    __syncthreads();

    // Normalize, add x, write out[b][d][k][q] (coalesced along q)
    int b = bk >> 7;
    int k = bk & 127;
    const float* xb = x   + b * (N_ * Kd * S_) + k * S_ + q0;
    float*       ob = out + b * (N_ * Kd * S_) + k * S_ + q0;
    for (int idx = tid; idx < 16384; idx += 256) {
        int d  = idx >> 6;
        int qi = idx & 63;
        float v = Rs[qi * 257 + d] + Os[qi * 264 + d];
        float o = (v - muA[qi]) * rsA[qi] * w2[d] + b2[d];
        ob[d * (Kd * S_) + qi] = o + xb[d * (Kd * S_) + qi];
    }
}

// ---------------------------------------------------------------------------
extern "C" void kernel_launch(void* const* d_in, const int* in_sizes, int n_in,
                              void* d_out, int out_size) {
    const float* x    = (const float*)d_in[0];
    const float* ln1w = (const float*)d_in[1];
    const float* ln1b = (const float*)d_in[2];
    const float* qw   = (const float*)d_in[3];
    const float* qb   = (const float*)d_in[4];
    const float* kw   = (const float*)d_in[5];
    const float* kb   = (const float*)d_in[6];
    const float* vw   = (const float*)d_in[7];
    const float* vb   = (const float*)d_in[8];
    const float* w2   = (const float*)d_in[9];
    const float* b2   = (const float*)d_in[10];
    float* out = (float*)d_out;

    pe_kernel<<<N_, S_>>>();
    ln1_kernel<<<BKt, 256>>>(x, ln1w, ln1b);
    qkv_gemm<<<dim3(4, 3, BKt), 256>>>(qw, kw, vw, qb, kb, vb);
    cudaFuncSetAttribute(attn_kernel, cudaFuncAttributeMaxDynamicSharedMemorySize, SMEM_BYTES);
    attn_kernel<<<dim3(4, BKt), 256, SMEM_BYTES>>>(x, out, w2, b2);
}

// round 2
// speedup vs baseline: 1.0010x; 1.0010x over previous
#include <cuda_runtime.h>
#include <math.h>

// Problem constants
#define B_   4
#define N_   256      // d_model
#define Kd   128      // K dim of x
#define S_   256      // sequence length
#define BKt  512      // B_*Kd batches
#define SCALE 0.0625f // 1/sqrt(256)

// Scratch (device globals; allocation APIs are forbidden)
__device__ float g_peT[N_ * S_];                      // [n][s]
__device__ float g_hT [BKt * N_ * S_];                // [bk][n][s]   LN1+PE output (transposed)
__device__ float g_Qt [BKt * N_ * S_];                // [bk][j][s]
__device__ float g_Kt [BKt * N_ * S_];                // [bk][j][s]
__device__ float g_V  [BKt * N_ * S_];                // [bk][s][j]

// ---------------------------------------------------------------------------
// Kernel 0: positional encoding table, transposed layout peT[n][s]
// pe[s, 2i] = sin(s * exp(-2i*ln(1e4)/256)); pe[s, 2i+1] = cos(...)
// ---------------------------------------------------------------------------
__global__ void pe_kernel() {
    int n = blockIdx.x;
    int s = threadIdx.x;
    float i2   = (float)(n & ~1);
    float freq = __expf(-i2 * (9.210340371976184f / 256.0f)); // ln(10000)/256
    float a    = (float)s * freq;
    g_peT[n * S_ + s] = (n & 1) ? cosf(a) : sinf(a);
}

// ---------------------------------------------------------------------------
// Kernel 1: LN1 over n per (bk, s) row + PE, write transposed hT[bk][n][s].
// One CTA per batch bk; thread t = s. All global accesses coalesced.
// x index: ((b*N_ + n)*Kd + k)*S_ + s
// ---------------------------------------------------------------------------
__global__ void __launch_bounds__(256) ln1_kernel(const float* __restrict__ x,
                                                  const float* __restrict__ w1,
                                                  const float* __restrict__ b1) {
    int bk = blockIdx.x;
    int b  = bk >> 7;
    int k  = bk & 127;
    int s  = threadIdx.x;
    const float* xp = x + b * (N_ * Kd * S_) + k * S_ + s; // stride per n: Kd*S_ = 32768

    float sum = 0.f, sq = 0.f;
#pragma unroll 4
    for (int n = 0; n < N_; n++) {
        float v = xp[n * (Kd * S_)];
        sum += v; sq += v * v;
    }
    float mu  = sum * (1.f / N_);
    float var = sq * (1.f / N_) - mu * mu;
    float rs  = rsqrtf(var + 1e-5f);

    float* hp = g_hT + bk * (N_ * S_) + s;
#pragma unroll 4
    for (int n = 0; n < N_; n++) {
        float v = xp[n * (Kd * S_)];
        hp[n * S_] = (v - mu) * rs * w1[n] + b1[n] + g_peT[n * S_ + s];
    }
}

// ---------------------------------------------------------------------------
// Kernel 2: per-batch GEMMs.
//   which=0/1 (Q/K):  out[bk][j][s] = sum_n W[j][n] * hT[bk][n][s] + bias[j]
//   which=2   (V)  :  out[bk][s][j] = sum_n W[j][n] * hT[bk][n][s] + bias[j]
// Block tile 128x128, K-chunk 8, 8x8 micro-tile per thread (256 threads).
// ---------------------------------------------------------------------------
__global__ void __launch_bounds__(256) qkv_gemm(const float* __restrict__ qw,
                                                const float* __restrict__ kw,
                                                const float* __restrict__ vw,
                                                const float* __restrict__ qb,
                                                const float* __restrict__ kb,
                                                const float* __restrict__ vb) {
    __shared__ __align__(16) float Ws[8][136];
    __shared__ __align__(16) float Hs[8][136];

    int bk    = blockIdx.z;
    int which = blockIdx.y;
    int r0    = (blockIdx.x >> 1) * 128;  // output row tile
    int c0    = (blockIdx.x & 1) * 128;   // output col tile

    const float* W    = (which == 0) ? qw : (which == 1) ? kw : vw;
    const float* bias = (which == 0) ? qb : (which == 1) ? kb : vb;
    float* out        = (which == 0) ? g_Qt : (which == 1) ? g_Kt : g_V;
    bool vmode = (which == 2);

    int j0 = vmode ? c0 : r0;   // W-row tile
    int s0 = vmode ? r0 : c0;   // h-col tile

    int tid = threadIdx.x;
    int ty  = tid >> 4;      // 0..15 (row dir)
    int tx  = tid & 15;      // 0..15 (col dir)

    const float* hbase = g_hT + bk * (N_ * S_);

    int hR = tid >> 5;            // 0..7
    int hC = (tid & 31) * 4;      // 0..124
    int wJ = tid >> 1;            // 0..127
    int wH = (tid & 1) * 4;       // 0 or 4

    float acc[8][8] = {};

    for (int n0 = 0; n0 < N_; n0 += 8) {
        __syncthreads();
        // Hs[nn][ss] <- hT[n0+nn][s0+ss]  (coalesced)
        float4 hv = *(const float4*)(hbase + (n0 + hR) * S_ + s0 + hC);
        *(float4*)&Hs[hR][hC] = hv;
        // Ws[nn][jj] <- W[j0+jj][n0+nn]   (transpose on store)
        float4 wv = *(const float4*)(W + (j0 + wJ) * N_ + n0 + wH);
        Ws[wH + 0][wJ] = wv.x;
        Ws[wH + 1][wJ] = wv.y;
        Ws[wH + 2][wJ] = wv.z;
        Ws[wH + 3][wJ] = wv.w;
        __syncthreads();

#pragma unroll
        for (int nn = 0; nn < 8; nn++) {
            float rv[8], cv[8];
            if (!vmode) {
                *(float4*)(rv)     = *(float4*)&Ws[nn][ty * 8];
                *(float4*)(rv + 4) = *(float4*)&Ws[nn][ty * 8 + 4];
                *(float4*)(cv)     = *(float4*)&Hs[nn][tx * 8];
                *(float4*)(cv + 4) = *(float4*)&Hs[nn][tx * 8 + 4];
            } else {
                *(float4*)(rv)     = *(float4*)&Hs[nn][ty * 8];
                *(float4*)(rv + 4) = *(float4*)&Hs[nn][ty * 8 + 4];
                *(float4*)(cv)     = *(float4*)&Ws[nn][tx * 8];
                *(float4*)(cv + 4) = *(float4*)&Ws[nn][tx * 8 + 4];
            }
#pragma unroll
            for (int i = 0; i < 8; i++)
#pragma unroll
                for (int c = 0; c < 8; c++)
                    acc[i][c] += rv[i] * cv[c];
        }
    }

    float* obase = out + bk * (N_ * S_);
#pragma unroll
    for (int i = 0; i < 8; i++) {
        int r = r0 + ty * 8 + i;
        float vals[8];
#pragma unroll
        for (int c = 0; c < 8; c++) {
            int cc = c0 + tx * 8 + c;
            float bb = vmode ? bias[cc] : bias[r];
            vals[c] = acc[i][c] + bb;
        }
        *(float4*)(obase + r * S_ + c0 + tx * 8)     = *(float4*)(vals);
        *(float4*)(obase + r * S_ + c0 + tx * 8 + 4) = *(float4*)(vals + 4);
    }
}

// ---------------------------------------------------------------------------
// Kernel 3: fused attention + residual + LN2 + final residual (+x), per
// (batch bk, 64-row q-block). 256 threads = 8 warps; warp w owns q rows
// w*8..w*8+7 (full softmax row lives inside one warp -> register softmax).
// ---------------------------------------------------------------------------
#define SM_QS   0
#define SM_PS   16384                 // 64 x 264
#define SM_OS   (16384 + 16896)      // 64 x 264
#define SM_TS   (16384 + 2 * 16896)  // 8 x 264 streaming tile
#define SM_MU   (SM_TS + 2112)
#define SM_RS   (SM_MU + 64)
#define SM_FLOATS (SM_RS + 64)
#define SMEM_BYTES (SM_FLOATS * 4)

__global__ void __launch_bounds__(256) attn_kernel(const float* __restrict__ x,
                                                   float* __restrict__ out,
                                                   const float* __restrict__ w2,
                                                   const float* __restrict__ b2) {
    extern __shared__ __align__(16) float sm[];
    float* Qs  = sm + SM_QS;   // [256 j][64 q]
    float* Ps  = sm + SM_PS;   // [64 q][264] probs (later reused as Rs, stride 257)
    float* Os  = sm + SM_OS;   // [64 q][264] att@V
    float* Ts  = sm + SM_TS;   // [8][264] streamed K/V tile
    float* muA = sm + SM_MU;
    float* rsA = sm + SM_RS;

    int bk   = blockIdx.y;
    int q0   = blockIdx.x * 64;
    int tid  = threadIdx.x;
    int wq   = tid >> 5;   // warp id = q group
    int lane = tid & 31;

    const float* Qb = g_Qt + bk * (N_ * S_);
    const float* Kb = g_Kt + bk * (N_ * S_);
    const float* Vb = g_V  + bk * (N_ * S_);
    const float* hb = g_hT + bk * (N_ * S_);

    // Phase A: load Q block Qs[j][qi]
    for (int idx4 = tid; idx4 < 4096; idx4 += 256) {
        int j  = idx4 >> 4;
        int q4 = (idx4 & 15) * 4;
        *(float4*)&Qs[j * 64 + q4] = *(const float4*)(Qb + j * S_ + q0 + q4);
    }

    // Phase B: logits L[q][k] = sum_j Qt[j][q] * Kt[j][k]
    float acc[8][8] = {};
    for (int j0 = 0; j0 < N_; j0 += 8) {
        __syncthreads();
        for (int idx4 = tid; idx4 < 512; idx4 += 256) {
            int r  = idx4 >> 6;
            int c4 = (idx4 & 63) * 4;
            *(float4*)&Ts[r * 264 + c4] = *(const float4*)(Kb + (j0 + r) * S_ + c4);
        }
        __syncthreads();
#pragma unroll
        for (int jj = 0; jj < 8; jj++) {
            float qv[8], kv[8];
            *(float4*)(qv)     = *(float4*)&Qs[(j0 + jj) * 64 + wq * 8];
            *(float4*)(qv + 4) = *(float4*)&Qs[(j0 + jj) * 64 + wq * 8 + 4];
            *(float4*)(kv)     = *(float4*)&Ts[jj * 264 + lane * 8];
            *(float4*)(kv + 4) = *(float4*)&Ts[jj * 264 + lane * 8 + 4];
#pragma unroll
            for (int i = 0; i < 8; i++)
#pragma unroll
                for (int c = 0; c < 8; c++)
                    acc[i][c] += qv[i] * kv[c];
        }
    }

    // Register softmax per q row (row fully inside one warp), then *SCALE
#pragma unroll
    for (int i = 0; i < 8; i++) {
        float m = -1e30f;
#pragma unroll
        for (int c = 0; c < 8; c++) m = fmaxf(m, acc[i][c]);
#pragma unroll
        for (int o = 16; o > 0; o >>= 1) m = fmaxf(m, __shfl_xor_sync(0xffffffffu, m, o));
        float ssum = 0.f;
#pragma unroll
        for (int c = 0; c < 8; c++) { acc[i][c] = __expf(acc[i][c] - m); ssum += acc[i][c]; }
#pragma unroll
        for (int o = 16; o > 0; o >>= 1) ssum += __shfl_xor_sync(0xffffffffu, ssum, o);
        float f = SCALE / ssum;
#pragma unroll
        for (int c = 0; c < 8; c++) acc[i][c] *= f;
        *(float4*)&Ps[(wq * 8 + i) * 264 + lane * 8]     = *(float4*)&acc[i][0];
        *(float4*)&Ps[(wq * 8 + i) * 264 + lane * 8 + 4] = *(float4*)&acc[i][4];
    }

    // Phase C: O[q][d] = sum_k P[q][k] * V[k][d]
    float acc2[8][8] = {};
    for (int k0 = 0; k0 < S_; k0 += 8) {
        __syncthreads();
        for (int idx4 = tid; idx4 < 512; idx4 += 256) {
            int r  = idx4 >> 6;
            int c4 = (idx4 & 63) * 4;
            *(float4*)&Ts[r * 264 + c4] = *(const float4*)(Vb + (k0 + r) * S_ + c4);
        }
        __syncthreads();
#pragma unroll
        for (int kk = 0; kk < 8; kk++) {
            float pv[8], vv[8];
#pragma unroll
            for (int i = 0; i < 8; i++) pv[i] = Ps[(wq * 8 + i) * 264 + k0 + kk];
            *(float4*)(vv)     = *(float4*)&Ts[kk * 264 + lane * 8];
            *(float4*)(vv + 4) = *(float4*)&Ts[kk * 264 + lane * 8 + 4];
#pragma unroll
            for (int i = 0; i < 8; i++)
#pragma unroll
                for (int c = 0; c < 8; c++)
                    acc2[i][c] += pv[i] * vv[c];
        }
    }

    // Stage O to smem
#pragma unroll
    for (int i = 0; i < 8; i++) {
        *(float4*)&Os[(wq * 8 + i) * 264 + lane * 8]     = *(float4*)&acc2[i][0];
        *(float4*)&Os[(wq * 8 + i) * 264 + lane * 8 + 4] = *(float4*)&acc2[i][4];
    }
    __syncthreads();

    // Load residual tile Rs[qi][d] (reuse Ps region, stride 257: conflict-free)
    float* Rs = Ps;
    for (int idx = tid; idx < 16384; idx += 256) {
        int d  = idx >> 6;
        int qi = idx & 63;
        Rs[qi * 257 + d] = hb[d * S_ + q0 + qi];
    }
    __syncthreads();

    // LN2 stats per q row (warp wq handles rows wq*8..wq*8+7)
    for (int ri = 0; ri < 8; ri++) {
        int r = wq * 8 + ri;
        float s1 = 0.f, s2 = 0.f;
#pragma unroll
        for (int c = 0; c < 8; c++) {
            int d = lane * 8 + c;
            float v = Rs[r * 257 + d] + Os[r * 264 + d];
            s1 += v; s2 += v * v;
        }
#pragma unroll
        for (int o = 16; o > 0; o >>= 1) {
            s1 += __shfl_xor_sync(0xffffffffu, s1, o);
            s2 += __shfl_xor_sync(0xffffffffu, s2, o);
        }
        float mu  = s1 * (1.f / N_);
        float var = s2 * (1.f / N_) - mu * mu;
        muA[r] = mu;
        rsA[r] = rsqrtf(var + 1e-5f);
    }
    __syncthreads();

    // Normalize, add x, write out[b][d][k][q] (coalesced along q)
    int b = bk >> 7;
    int k = bk & 127;
    const float* xb = x   + b * (N_ * Kd * S_) + k * S_ + q0;
    float*       ob = out + b * (N_ * Kd * S_) + k * S_ + q0;
    for (int idx = tid; idx < 16384; idx += 256) {
        int d  = idx >> 6;
        int qi = idx & 63;
        float v = Rs[qi * 257 + d] + Os[qi * 264 + d];
        float o = (v - muA[qi]) * rsA[qi] * w2[d] + b2[d];
        ob[d * (Kd * S_) + qi] = o + xb[d * (Kd * S_) + qi];
    }
}

// ---------------------------------------------------------------------------
extern "C" void kernel_launch(void* const* d_in, const int* in_sizes, int n_in,
                              void* d_out, int out_size) {
    const float* x    = (const float*)d_in[0];
    const float* ln1w = (const float*)d_in[1];
    const float* ln1b = (const float*)d_in[2];
    const float* qw   = (const float*)d_in[3];
    const float* qb   = (const float*)d_in[4];
    const float* kw   = (const float*)d_in[5];
    const float* kb   = (const float*)d_in[6];
    const float* vw   = (const float*)d_in[7];
    const float* vb   = (const float*)d_in[8];
    const float* w2   = (const float*)d_in[9];
    const float* b2   = (const float*)d_in[10];
    float* out = (float*)d_out;

    pe_kernel<<<N_, S_>>>();
    ln1_kernel<<<BKt, 256>>>(x, ln1w, ln1b);
    qkv_gemm<<<dim3(4, 3, BKt), 256>>>(qw, kw, vw, qb, kb, vb);
    cudaFuncSetAttribute(attn_kernel, cudaFuncAttributeMaxDynamicSharedMemorySize, SMEM_BYTES);
    attn_kernel<<<dim3(4, BKt), 256, SMEM_BYTES>>>(x, out, w2, b2);
}

// round 4
// speedup vs baseline: 5.8691x; 5.8635x over previous
#include <cuda_runtime.h>
#include <cuda_bf16.h>
#include <math.h>
#include <stdint.h>

#define B_   4
#define N_   256
#define Kd   128
#define S_   256
#define BKt  512
#define BE   65536
#define SCALE 0.0625f

__device__ __align__(256) float          g_pe[S_ * N_];
__device__ __align__(256) float          g_h [BKt * BE];       // fp32 [bk][s][n]
__device__ __align__(256) __nv_bfloat16  g_hb[BKt * BE];       // bf16 [bk][s][n]
__device__ __align__(256) __nv_bfloat16  g_Qb[BKt * BE];       // [bk][s][j]
__device__ __align__(256) __nv_bfloat16  g_Kb[BKt * BE];       // [bk][k][j]
__device__ __align__(256) __nv_bfloat16  g_Vt[BKt * BE];       // [bk][j][s]
__device__ __align__(256) __nv_bfloat16  g_wb[3 * N_ * N_];    // q,k,v weights bf16 [j][n]

// ---------------- low-level helpers (sm_80-class, legal on plain sm_103) ----
__device__ __forceinline__ uint32_t smem_u32(const void* p) {
    uint32_t a;
    asm("{ .reg .u64 t; cvta.to.shared.u64 t, %1; cvt.u32.u64 %0, t; }" : "=r"(a) : "l"(p));
    return a;
}
__device__ __forceinline__ void cpasync16(uint32_t dst, const void* src) {
    asm volatile("cp.async.cg.shared.global [%0], [%1], 16;" :: "r"(dst), "l"(src));
}
#define CP_COMMIT() asm volatile("cp.async.commit_group;" ::: "memory")
#define CP_WAIT0()  asm volatile("cp.async.wait_group 0;" ::: "memory")
#define CP_WAIT1()  asm volatile("cp.async.wait_group 1;" ::: "memory")

__device__ __forceinline__ void ldmat4(uint32_t& r0, uint32_t& r1, uint32_t& r2, uint32_t& r3, uint32_t addr) {
    asm volatile("ldmatrix.sync.aligned.m8n8.x4.shared.b16 {%0,%1,%2,%3}, [%4];"
                 : "=r"(r0), "=r"(r1), "=r"(r2), "=r"(r3) : "r"(addr));
}
__device__ __forceinline__ void mma16816(float* d, const uint32_t* a, const uint32_t* b) {
    asm volatile("mma.sync.aligned.m16n8k16.row.col.f32.bf16.bf16.f32 "
                 "{%0,%1,%2,%3},{%4,%5,%6,%7},{%8,%9},{%0,%1,%2,%3};"
                 : "+f"(d[0]), "+f"(d[1]), "+f"(d[2]), "+f"(d[3])
                 : "r"(a[0]), "r"(a[1]), "r"(a[2]), "r"(a[3]), "r"(b[0]), "r"(b[1]));
}

// gmem [rows x 64] bf16 (row stride 256 elems) -> smem SW128 [rows][128B]
__device__ __forceinline__ void tile_cp(uint32_t dst, const __nv_bfloat16* __restrict__ src,
                                        int rows, int tid, int nthr) {
    int total = rows * 8;
    for (int u = tid; u < total; u += nthr) {
        int row = u >> 3, seg = u & 7;
        cpasync16(dst + row * 128 + (((uint32_t)(seg ^ (row & 7))) << 4), src + row * 256 + seg * 8);
    }
}
// A fragment address (m16k16 tile at row m0, k-seg ksg)
__device__ __forceinline__ uint32_t a_addr(uint32_t base, int m0, int ksg, int lane) {
    int row = m0 + (lane & 15);
    int seg = ksg + (lane >> 4);
    return base + row * 128 + (((uint32_t)(seg ^ (row & 7))) << 4);
}
// B fragment address (.x4 -> two n8k16 frags at rows n0..n0+15)
__device__ __forceinline__ uint32_t b_addr(uint32_t base, int n0, int ksg, int lane) {
    int row = n0 + ((lane >> 4) << 3) + (lane & 7);
    int seg = ksg + ((lane >> 3) & 1);
    return base + row * 128 + (((uint32_t)(seg ^ (row & 7))) << 4);
}

// ---------------------------------------------------------------------------
__global__ void pe_kernel() {
    int s = blockIdx.x, n = threadIdx.x;
    float freq = __expf(-(float)(n & ~1) * (9.210340371976184f / 256.0f));
    float a = (float)s * freq;
    g_pe[s * N_ + n] = (n & 1) ? cosf(a) : sinf(a);
}

__global__ void wconv_kernel(const float* __restrict__ qw, const float* __restrict__ kw,
                             const float* __restrict__ vw) {
    int i = blockIdx.x * 256 + threadIdx.x;
    const float* src = (i < 65536) ? qw : ((i < 131072) ? kw : vw);
    g_wb[i] = __float2bfloat16(src[i & 65535]);
}

__global__ void __launch_bounds__(256) ln1_kernel(const float* __restrict__ x,
                                                  const float* __restrict__ w1,
                                                  const float* __restrict__ b1) {
    __shared__ float xs[32 * 257];
    __shared__ float muS[256], rsS[256], w1s[256], b1s[256];
    int bk = blockIdx.x;
    int b = bk >> 7, k = bk & 127;
    int tid = threadIdx.x;
    const float* xb = x + ((size_t)b * N_ * Kd + k) * S_;

    float s1 = 0.f, s2 = 0.f;
#pragma unroll 4
    for (int n = 0; n < N_; n++) {
        float v = xb[n * (Kd * S_) + tid];
        s1 += v; s2 += v * v;
    }
    float mu = s1 * (1.f / N_);
    float var = s2 * (1.f / N_) - mu * mu;
    muS[tid] = mu;
    rsS[tid] = rsqrtf(var + 1e-5f);
    w1s[tid] = w1[tid];
    b1s[tid] = b1[tid];
    __syncthreads();

    float* h = g_h + (size_t)bk * BE;
    __nv_bfloat16* hb = g_hb + (size_t)bk * BE;
    int wid = tid >> 5, lane = tid & 31;
    for (int t = 0; t < 8; t++) {
        int n0 = t * 32;
#pragma unroll 4
        for (int it = 0; it < 32; it++)
            xs[it * 257 + tid] = xb[(n0 + it) * (Kd * S_) + tid];
        __syncthreads();
#pragma unroll 4
        for (int j = 0; j < 32; j++) {
            int s = wid * 32 + j;
            int n = n0 + lane;
            float v  = xs[lane * 257 + s];
            float hv = (v - muS[s]) * rsS[s] * w1s[n] + b1s[n] + g_pe[s * N_ + n];
            h [s * N_ + n] = hv;
            hb[s * N_ + n] = __float2bfloat16(hv);
        }
        __syncthreads();
    }
}

// ---------------- qkv_mma: 128x128 CTA tile, K=256, mma.sync bf16 -----------
#define Q_A0   0
#define Q_A1   16384
#define Q_B0   32768
#define Q_B1   49152
#define Q_BIAS 65536
#define Q_SMEM 66560

__global__ void __launch_bounds__(256, 2)
qkv_mma(const float* __restrict__ qb_, const float* __restrict__ kb_, const float* __restrict__ vb_) {
    extern __shared__ char smem_dyn[];
    uint32_t sb = smem_u32(smem_dyn);
    int tid = threadIdx.x, lane = tid & 31, wid = tid >> 5;
    int wm = wid >> 2, wn = wid & 3;          // warps 2(m) x 4(n)
    int m_base = wm * 64, n_base = wn * 32;

    int mt = blockIdx.x >> 1, nt = blockIdx.x & 1;
    int which = blockIdx.y, bk = blockIdx.z;

    const __nv_bfloat16* hb = g_hb + (size_t)bk * BE;
    const __nv_bfloat16 *Ag, *Bg;
    const float* bias;
    __nv_bfloat16* outp;
    if (which == 0)      { Ag = hb + mt * 128 * 256;              Bg = g_wb + nt * 128 * 256;          bias = qb_; outp = g_Qb + (size_t)bk * BE; }
    else if (which == 1) { Ag = hb + mt * 128 * 256;              Bg = g_wb + 65536 + nt * 128 * 256;  bias = kb_; outp = g_Kb + (size_t)bk * BE; }
    else                 { Ag = g_wb + 131072 + mt * 128 * 256;   Bg = hb + nt * 128 * 256;            bias = vb_; outp = g_Vt + (size_t)bk * BE; }

    float* biass = (float*)(smem_dyn + Q_BIAS);
    for (int i = tid; i < 256; i += 256) biass[i] = bias[i];

    float acc[4][4][4] = {};

    tile_cp(sb + Q_A0, Ag, 128, tid, 256);
    tile_cp(sb + Q_B0, Bg, 128, tid, 256);
    CP_COMMIT();

    for (int c = 0; c < 4; c++) {
        int cur = c & 1;
        if (c + 1 < 4) {
            tile_cp(sb + (cur ? Q_A0 : Q_A1), Ag + (c + 1) * 64, 128, tid, 256);
            tile_cp(sb + (cur ? Q_B0 : Q_B1), Bg + (c + 1) * 64, 128, tid, 256);
            CP_COMMIT();
            CP_WAIT1();
        } else {
            CP_WAIT0();
        }
        __syncthreads();
        uint32_t aB = sb + (cur ? Q_A1 : Q_A0);
        uint32_t bB = sb + (cur ? Q_B1 : Q_B0);
#pragma unroll
        for (int kk = 0; kk < 4; kk++) {
            int ksg = kk * 2;
            uint32_t a[4][4];
#pragma unroll
            for (int mi = 0; mi < 4; mi++)
                ldmat4(a[mi][0], a[mi][1], a[mi][2], a[mi][3], a_addr(aB, m_base + mi * 16, ksg, lane));
            uint32_t bfr[4][2];
#pragma unroll
            for (int nj = 0; nj < 2; nj++) {
                uint32_t r0, r1, r2, r3;
                ldmat4(r0, r1, r2, r3, b_addr(bB, n_base + nj * 16, ksg, lane));
                bfr[nj * 2][0] = r0; bfr[nj * 2][1] = r1;
                bfr[nj * 2 + 1][0] = r2; bfr[nj * 2 + 1][1] = r3;
            }
#pragma unroll
            for (int mi = 0; mi < 4; mi++)
#pragma unroll
                for (int ni = 0; ni < 4; ni++)
                    mma16816(acc[mi][ni], a[mi], bfr[ni]);
        }
        __syncthreads();
    }

    // epilogue: bias + bf16 store
#pragma unroll
    for (int mi = 0; mi < 4; mi++) {
#pragma unroll
        for (int h = 0; h < 2; h++) {
            int rloc = m_base + mi * 16 + h * 8 + (lane >> 2);
            int grow = mt * 128 + rloc;
            float rb = (which == 2) ? biass[grow] : 0.f;
#pragma unroll
            for (int ni = 0; ni < 4; ni++) {
                int cloc = n_base + ni * 8 + (lane & 3) * 2;
                int gcol = nt * 128 + cloc;
                float v0 = acc[mi][ni][h * 2 + 0];
                float v1 = acc[mi][ni][h * 2 + 1];
                if (which == 2) { v0 += rb; v1 += rb; }
                else { v0 += biass[gcol]; v1 += biass[gcol + 1]; }
                __nv_bfloat162 t = __floats2bfloat162_rn(v0, v1);
                *(uint32_t*)(outp + grow * 256 + gcol) = *(uint32_t*)&t;
            }
        }
    }
}

// ---------------- attn_mma: per (bk, 64-q tile) ------------------------------
#define A_QS   0        // 4 chunks x [64][128B] = 32768
#define A_BS   32768    // [256][128B] = 32768
#define A_PS   65536    // 4 chunks x [64][128B] = 32768
#define A_RED  98304    // [4][64] fp32
#define A_FR   99328    // [64] fp32
#define A_MU   99584
#define A_RS   99840
#define A_W2   100096
#define A_B2   101120
#define A_SMEM 102144
// epilogue Os reuses [0 .. 98304): [64][265] fp32 = 67840 B

__global__ void __launch_bounds__(256, 2)
attn_mma(const float* __restrict__ x, float* __restrict__ out,
         const float* __restrict__ w2, const float* __restrict__ b2) {
    extern __shared__ char smem_dyn[];
    uint32_t sb = smem_u32(smem_dyn);
    int tid = threadIdx.x, lane = tid & 31, wid = tid >> 5;
    int wm = wid >> 2, wn = wid & 3;          // warps 2(m=q) x 4(n)
    int q0 = blockIdx.x * 64;
    int bk = blockIdx.y;

    float* sRed = (float*)(smem_dyn + A_RED);
    float* frow = (float*)(smem_dyn + A_FR);
    float* muA  = (float*)(smem_dyn + A_MU);
    float* rsA  = (float*)(smem_dyn + A_RS);
    float* w2s  = (float*)(smem_dyn + A_W2);
    float* b2s  = (float*)(smem_dyn + A_B2);
    for (int i = tid; i < 256; i += 256) { w2s[i] = w2[i]; b2s[i] = b2[i]; }

    const __nv_bfloat16* Qg = g_Qb + (size_t)bk * BE + q0 * 256;
    const __nv_bfloat16* Kg = g_Kb + (size_t)bk * BE;
    const __nv_bfloat16* Vg = g_Vt + (size_t)bk * BE;

    float acc[2][8][4] = {};

    // ---- phase 1: logits S[64 x 256] = Q . K^T ----
    for (int jc = 0; jc < 4; jc++)
        tile_cp(sb + A_QS + jc * 8192, Qg + jc * 64, 64, tid, 256);
    CP_COMMIT();
    for (int jc = 0; jc < 4; jc++) {
        tile_cp(sb + A_BS, Kg + jc * 64, 256, tid, 256);
        CP_COMMIT(); CP_WAIT0();
        __syncthreads();
        uint32_t aB = sb + A_QS + jc * 8192;
#pragma unroll
        for (int kk = 0; kk < 4; kk++) {
            int ksg = kk * 2;
            uint32_t a[2][4];
#pragma unroll
            for (int mi = 0; mi < 2; mi++)
                ldmat4(a[mi][0], a[mi][1], a[mi][2], a[mi][3], a_addr(aB, wm * 32 + mi * 16, ksg, lane));
#pragma unroll
            for (int nj = 0; nj < 4; nj++) {
                uint32_t r0, r1, r2, r3;
                ldmat4(r0, r1, r2, r3, b_addr(sb + A_BS, wn * 64 + nj * 16, ksg, lane));
                uint32_t b0[2] = {r0, r1}, b1[2] = {r2, r3};
#pragma unroll
                for (int mi = 0; mi < 2; mi++) {
                    mma16816(acc[mi][nj * 2],     a[mi], b0);
                    mma16816(acc[mi][nj * 2 + 1], a[mi], b1);
                }
            }
        }
        __syncthreads();
    }

    // ---- softmax across warps ----
#pragma unroll
    for (int mi = 0; mi < 2; mi++)
#pragma unroll
        for (int h = 0; h < 2; h++) {
            float pm = -1e30f;
#pragma unroll
            for (int ni = 0; ni < 8; ni++) {
                pm = fmaxf(pm, acc[mi][ni][h * 2 + 0]);
                pm = fmaxf(pm, acc[mi][ni][h * 2 + 1]);
            }
            pm = fmaxf(pm, __shfl_xor_sync(0xffffffffu, pm, 1));
            pm = fmaxf(pm, __shfl_xor_sync(0xffffffffu, pm, 2));
            if ((lane & 3) == 0)
                sRed[wn * 64 + wm * 32 + mi * 16 + h * 8 + (lane >> 2)] = pm;
        }
    __syncthreads();
    float rm[2][2];
#pragma unroll
    for (int mi = 0; mi < 2; mi++)
#pragma unroll
        for (int h = 0; h < 2; h++) {
            int r = wm * 32 + mi * 16 + h * 8 + (lane >> 2);
            rm[mi][h] = fmaxf(fmaxf(sRed[r], sRed[64 + r]), fmaxf(sRed[128 + r], sRed[192 + r]));
        }
    __syncthreads();
#pragma unroll
    for (int mi = 0; mi < 2; mi++)
#pragma unroll
        for (int h = 0; h < 2; h++) {
            int r = wm * 32 + mi * 16 + h * 8 + (lane >> 2);
            float ps = 0.f;
#pragma unroll
            for (int ni = 0; ni < 8; ni++) {
                float e0 = __expf(acc[mi][ni][h * 2 + 0] - rm[mi][h]);
                float e1 = __expf(acc[mi][ni][h * 2 + 1] - rm[mi][h]);
                ps += e0 + e1;
                __nv_bfloat162 t = __floats2bfloat162_rn(e0, e1);
                int cl = (wn * 64 + ni * 8 + (lane & 3) * 2) & 63;   // col within chunk wn
                int cb = cl * 2;
                uint32_t addr = sb + A_PS + wn * 8192 + r * 128
                              + (((uint32_t)((cb >> 4) ^ (r & 7))) << 4) + (cb & 15);
                asm volatile("st.shared.b32 [%0], %1;" :: "r"(addr), "r"(*(uint32_t*)&t));
            }
            ps += __shfl_xor_sync(0xffffffffu, ps, 1);
            ps += __shfl_xor_sync(0xffffffffu, ps, 2);
            if ((lane & 3) == 0) sRed[wn * 64 + r] = ps;
        }
    __syncthreads();
    if (tid < 64)
        frow[tid] = SCALE / (sRed[tid] + sRed[64 + tid] + sRed[128 + tid] + sRed[192 + tid]);
    // zero accumulators for phase 2
#pragma unroll
    for (int mi = 0; mi < 2; mi++)
#pragma unroll
        for (int ni = 0; ni < 8; ni++)
#pragma unroll
            for (int j = 0; j < 4; j++) acc[mi][ni][j] = 0.f;
    __syncthreads();

    // ---- phase 2: O[64 x 256] = expP . Vt^T ----
    for (int sc = 0; sc < 4; sc++) {
        tile_cp(sb + A_BS, Vg + sc * 64, 256, tid, 256);
        CP_COMMIT(); CP_WAIT0();
        __syncthreads();
        uint32_t aB = sb + A_PS + sc * 8192;
#pragma unroll
        for (int kk = 0; kk < 4; kk++) {
            int ksg = kk * 2;
            uint32_t a[2][4];
#pragma unroll
            for (int mi = 0; mi < 2; mi++)
                ldmat4(a[mi][0], a[mi][1], a[mi][2], a[mi][3], a_addr(aB, wm * 32 + mi * 16, ksg, lane));
#pragma unroll
            for (int nj = 0; nj < 4; nj++) {
                uint32_t r0, r1, r2, r3;
                ldmat4(r0, r1, r2, r3, b_addr(sb + A_BS, wn * 64 + nj * 16, ksg, lane));
                uint32_t b0[2] = {r0, r1}, b1[2] = {r2, r3};
#pragma unroll
                for (int mi = 0; mi < 2; mi++) {
                    mma16816(acc[mi][nj * 2],     a[mi], b0);
                    mma16816(acc[mi][nj * 2 + 1], a[mi], b1);
                }
            }
        }
        __syncthreads();
    }

    // ---- epilogue: v = h + O*f, LN2, +x ----
    float* Os = (float*)smem_dyn;   // [64][265]
    const float* hbase = g_h + (size_t)bk * BE;
#pragma unroll
    for (int mi = 0; mi < 2; mi++)
#pragma unroll
        for (int h = 0; h < 2; h++) {
            int r = wm * 32 + mi * 16 + h * 8 + (lane >> 2);
            float fr = frow[r];
            const float* hrow = hbase + (q0 + r) * 256;
#pragma unroll
            for (int ni = 0; ni < 8; ni++) {
                int d = wn * 64 + ni * 8 + (lane & 3) * 2;
                float2 hv = *(const float2*)(hrow + d);
                Os[r * 265 + d]     = hv.x + acc[mi][ni][h * 2 + 0] * fr;
                Os[r * 265 + d + 1] = hv.y + acc[mi][ni][h * 2 + 1] * fr;
            }
        }
    __syncthreads();

    {
        int r = tid >> 2, sub = tid & 3;
        float s1 = 0.f, s2 = 0.f;
#pragma unroll 8
        for (int j = 0; j < 64; j++) {
            float v = Os[r * 265 + sub * 64 + j];
            s1 += v; s2 += v * v;
        }
        s1 += __shfl_xor_sync(0xffffffffu, s1, 1); s2 += __shfl_xor_sync(0xffffffffu, s2, 1);
        s1 += __shfl_xor_sync(0xffffffffu, s1, 2); s2 += __shfl_xor_sync(0xffffffffu, s2, 2);
        if (sub == 0) {
            float mu = s1 * (1.f / N_);
            float var = s2 * (1.f / N_) - mu * mu;
            muA[r] = mu;
            rsA[r] = rsqrtf(var + 1e-5f);
        }
    }
    __syncthreads();

    int b = bk >> 7, kk2 = bk & 127;
    const float* xb = x   + (size_t)b * (N_ * Kd * S_) + kk2 * S_ + q0;
    float*       ob = out + (size_t)b * (N_ * Kd * S_) + kk2 * S_ + q0;
#pragma unroll 4
    for (int it = 0; it < 64; it++) {
        int idx = it * 256 + tid;
        int d = idx >> 6, qi = idx & 63;
        float v = Os[qi * 265 + d];
        float o = (v - muA[qi]) * rsA[qi] * w2s[d] + b2s[d] + xb[d * (Kd * S_) + qi];
        ob[d * (Kd * S_) + qi] = o;
    }
}

extern "C" void kernel_launch(void* const* d_in, const int* in_sizes, int n_in,
                              void* d_out, int out_size) {
    const float* x    = (const float*)d_in[0];
    const float* ln1w = (const float*)d_in[1];
    const float* ln1b = (const float*)d_in[2];
    const float* qw   = (const float*)d_in[3];
    const float* qb   = (const float*)d_in[4];
    const float* kw   = (const float*)d_in[5];
    const float* kb   = (const float*)d_in[6];
    const float* vw   = (const float*)d_in[7];
    const float* vb   = (const float*)d_in[8];
    const float* w2   = (const float*)d_in[9];
    const float* b2   = (const float*)d_in[10];
    float* out = (float*)d_out;

    cudaFuncSetAttribute(qkv_mma,  cudaFuncAttributeMaxDynamicSharedMemorySize, Q_SMEM);
    cudaFuncSetAttribute(attn_mma, cudaFuncAttributeMaxDynamicSharedMemorySize, A_SMEM);

    pe_kernel<<<S_, N_>>>();
    wconv_kernel<<<768, 256>>>(qw, kw, vw);
    ln1_kernel<<<BKt, 256>>>(x, ln1w, ln1b);
    qkv_mma<<<dim3(4, 3, BKt), 256, Q_SMEM>>>(qb, kb, vb);
    attn_mma<<<dim3(4, BKt), 256, A_SMEM>>>(x, out, w2, b2);
}